// round 13
// baseline (speedup 1.0000x reference)
#include <cuda_runtime.h>
#include <cuda_fp16.h>
#include <cstdint>

#define BATCH 16
#define CH 128          // channels == time steps == out channels
#define HH 112
#define WW 112
#define HW (HH * WW)

// ---------------- device globals (no allocation allowed) ----------------
__device__ float  g_G[256];
__device__ float  g_Bp[CH];
// A fragments (fused weights) in m16n8k16 A layout, fp16:
// [tap 9][cb 8][mtile 8][lane 32][8 halfs = a0..a3]
__device__ __half g_AFh[9 * 8 * 8 * 32 * 8];          // 294912 B
// Transposed fp16 x: [cb 8][b 16][h 112][w 112][ci16 permuted] as half2 pairs
__device__ __half2 g_Xt[(size_t)8 * BATCH * HH * WW * 8];   // 51.4 MB

__device__ __forceinline__ uint32_t smem_u32(const void* p) {
    uint32_t a;
    asm("{ .reg .u64 t; cvta.to.shared.u64 t, %1; cvt.u32.u64 %0, t; }" : "=r"(a) : "l"(p));
    return a;
}

// ---------------------------------------------------------------------------
// Merged: G[m] = (l conv k)[m] (alpha == beta == exp(-1) exactly), then
// fused bias Bp[t] = sum_o G[(t-o)&255] * b[o]. Single block.
// ---------------------------------------------------------------------------
__global__ void gb_kernel(const float* __restrict__ b) {
    __shared__ float Gs[256];
    int m = threadIdx.x;  // 256
    const float beta = 0.36787944117144233f;
    int lo = max(0, m - 127), hi = min(m, 127);
    int cnt = hi - lo + 1;
    float gv = (cnt > 0) ? (1.0f - beta) * expf(-(float)m) * (float)cnt : 0.0f;
    g_G[m] = gv;
    Gs[m] = gv;
    __syncthreads();
    if (m < CH) {
        float s = 0.0f;
        #pragma unroll 8
        for (int o = 0; o < CH; o++) s += Gs[(m - o) & 255] * b[o];
        g_Bp[m] = s;
    }
}

// ---------------------------------------------------------------------------
// Fused weights scattered into mma.m16n8k16 A-fragment layout (fp16).
// Wp[co][ci][tap] = sum_o G[(co-o)&255] * W[o][ci][tap]
// ---------------------------------------------------------------------------
__global__ void w2_kernel(const float* __restrict__ W) {
    __shared__ float Ws[128];
    __shared__ float Gs[256];
    int blk = blockIdx.x;               // ci*9 + tap : 1152 blocks
    int ci = blk / 9, tap = blk - ci * 9;
    int co = threadIdx.x;               // 128 threads
    Ws[co] = W[co * 1152 + ci * 9 + tap];
    Gs[co] = g_G[co];
    Gs[co + 128] = g_G[co + 128];
    __syncthreads();
    float s = 0.0f;
    #pragma unroll 8
    for (int o = 0; o < 128; o++) s += Gs[(co - o) & 255] * Ws[o];

    int r = co & 15, mt = co >> 4;
    int g = r & 7, rh = r >> 3;                 // rh -> a1/a3 (row+8)
    int kc = ci >> 4, c16 = ci & 15;
    int tg = (c16 >> 1) & 3, bslot = c16 & 1, c = c16 >> 3;   // c -> k+8 (a2/a3)
    int reg = rh + 2 * c;
    int lane = g * 4 + tg;
    g_AFh[((((size_t)tap * 8 + kc) * 8 + mt) * 32 + lane) * 8 + reg * 2 + bslot] =
        __float2half_rn(s);
}

// ---------------------------------------------------------------------------
// Transpose x -> fp16 [cb][b][h][w][ci16 perm] (32B per w).
// 2 h-rows per 256-thread block: 896B contiguous reads, 2x7168B writes.
// half2 slot p2 = tg*2 + c holds (ci, ci+1), ci = 2*tg + 8*c.
// ---------------------------------------------------------------------------
__global__ void xt_kernel(const float* __restrict__ x) {
    __shared__ float t[16][2][116];
    int h0 = blockIdx.x * 2, cb = blockIdx.y, b = blockIdx.z;
    int tid = threadIdx.x;   // 256
    const float* xp = x + ((size_t)b * CH + cb * 16) * HW + h0 * WW;
    // 16 ci x 56 float4 (rows h0, h0+1 are contiguous: 224 floats per ci)
    for (int i = tid; i < 16 * 56; i += 256) {
        int ci = i / 56, k = i - ci * 56;
        int hh = (k >= 28) ? 1 : 0;
        int w4 = k - hh * 28;
        ((float4*)t[ci][hh])[w4] =
            *(const float4*)(xp + (size_t)ci * HW + hh * WW + w4 * 4);
    }
    __syncthreads();
    // 448 slots: (hh, w, half16B). 8 LDS + 4 cvt + 1 STG.128 per slot.
    for (int i = tid; i < 448; i += 256) {
        int hh = (i >= 224) ? 1 : 0;
        int j = i - hh * 224;
        int w = j >> 1, hf = j & 1;
        uint32_t h2[4];
        #pragma unroll
        for (int q = 0; q < 4; q++) {
            int p2 = hf * 4 + q;
            int tg = p2 >> 1, c = p2 & 1;
            int ca = 2 * tg + 8 * c;
            __half2 v = __floats2half2_rn(t[ca][hh][w], t[ca + 1][hh][w]);
            h2[q] = *(uint32_t*)&v;
        }
        __half2* dst = g_Xt + ((((size_t)cb * BATCH + b) * HH + h0 + hh) * WW) * 8;
        *((uint4*)(dst + (size_t)w * 8) + hf) = make_uint4(h2[0], h2[1], h2[2], h2[3]);
    }
}

// ---------------------------------------------------------------------------
// Main conv: implicit GEMM on mma.sync.m16n8k16 fp16 (f32 accum).
// CTA = (b, h), 128 threads, 4 warps in 2M x 2N; warp tile 64co x 56px.
// A fragments register-double-buffered across taps; ONE sync per chunk
// (wait -> sync -> stage-next -> compute preserves overlap).
// ---------------------------------------------------------------------------
#define XBUF_BYTES 11520        // 3 * 120 * 32
#define NSLOT 720               // 3 * 120 * 2 (16B slots)

__global__ __launch_bounds__(128, 2) void conv_kernel(float* __restrict__ out) {
    __shared__ __align__(16) char xsm[2][XBUF_BYTES];
    __shared__ int otab[NSLOT];

    const int tid = threadIdx.x, wid = tid >> 5, lane = tid & 31;
    const int g = lane >> 2, tg = lane & 3;
    const int wm = wid >> 1, wn = wid & 1;    // 2x2 warp grid
    const int b = blockIdx.y;
    const int h = blockIdx.x;

    // ---- offset table (each thread writes and later reads the SAME indices)
    for (int i = tid; i < NSLOT; i += 128) {
        int blk = i & 1;
        int w = (i >> 1) % 120;
        int row = (i >> 1) / 120;
        int gh = h - 1 + row;
        int gw = w - 1;
        bool ok = ((unsigned)gh < (unsigned)HH) & ((unsigned)gw < (unsigned)WW);
        otab[i] = ok ? ((gh * WW + gw) * 32 + blk * 16) : -1;
    }

    // accumulators initialized with fused bias
    float acc[4][7][4];
    #pragma unroll
    for (int i = 0; i < 4; i++) {
        float blo = g_Bp[wm * 64 + i * 16 + g];
        float bhi = g_Bp[wm * 64 + i * 16 + g + 8];
        #pragma unroll
        for (int j = 0; j < 7; j++) {
            acc[i][j][0] = blo; acc[i][j][1] = blo;
            acc[i][j][2] = bhi; acc[i][j][3] = bhi;
        }
    }

    const uint4* AF4 = (const uint4*)g_AFh;
    const uint32_t xs_b = smem_u32(&xsm[0][0]);
    const char* xtb = (const char*)g_Xt;

    // ---- async stage one 16-ci chunk (fp16, 16B contiguous copies)
    auto stage = [&](int cb, int buf) {
        const char* src_base = xtb + (((size_t)cb * BATCH + b) * HH) * WW * 32;
        uint32_t d = xs_b + (uint32_t)buf * XBUF_BYTES + (uint32_t)tid * 16;
        #pragma unroll
        for (int it = 0; it < 6; it++) {
            int i = tid + it * 128;
            if (i < NSLOT) {
                int off = otab[i];
                const char* src = src_base + (off >= 0 ? off : 0);
                int sz = (off >= 0) ? 16 : 0;
                asm volatile("cp.async.ca.shared.global [%0], [%1], 16, %2;"
                             :: "r"(d), "l"(src), "r"(sz));
            }
            d += 2048;
        }
        asm volatile("cp.async.commit_group;" ::: "memory");
    };

    // A-fragment load for (tap, cb): 4 consecutive mtiles for this warp
    auto aload = [&](int tap, int cb, uint4* av) {
        #pragma unroll
        for (int i = 0; i < 4; i++)
            av[i] = __ldg(&AF4[(((size_t)tap * 8 + cb) * 8 + wm * 4 + i) * 32 + lane]);
    };

    stage(0, 0);   // prologue

    uint4 av_cur[4], av_nxt[4];
    aload(0, 0, av_cur);   // prefetch first tap

    for (int cb = 0; cb < 8; cb++) {
        asm volatile("cp.async.wait_group 0;" ::: "memory");
        __syncthreads();
        if (cb + 1 < 8) stage(cb + 1, (cb + 1) & 1);   // overlaps compute below

        // per-warp/lane B base: [row][w = wn*56 + g + (j*8+kw)][p = tg*4]
        const char* bp = &xsm[cb & 1][0] + (wn * 56 + g) * 32 + tg * 8;

        #pragma unroll
        for (int tap = 0; tap < 9; tap++) {
            // prefetch next tap's A fragments (cross chunk boundary)
            int ntap = (tap == 8) ? 0 : tap + 1;
            int ncb  = (tap == 8) ? ((cb + 1) & 7) : cb;
            aload(ntap, ncb, av_nxt);

            const int kh = tap / 3, kw = tap - kh * 3;
            #pragma unroll
            for (int j = 0; j < 7; j++) {
                // one LDS.64: {b0 = ci 2tg..2tg+1, b1 = ci 2tg+8..2tg+9}
                uint2 bv = *(const uint2*)(bp + kh * 3840 + (j * 8 + kw) * 32);
                #pragma unroll
                for (int i = 0; i < 4; i++) {
                    asm volatile(
                        "mma.sync.aligned.m16n8k16.row.col.f32.f16.f16.f32 "
                        "{%0,%1,%2,%3}, {%4,%5,%6,%7}, {%8,%9}, {%0,%1,%2,%3};"
                        : "+f"(acc[i][j][0]), "+f"(acc[i][j][1]),
                          "+f"(acc[i][j][2]), "+f"(acc[i][j][3])
                        : "r"(av_cur[i].x), "r"(av_cur[i].y),
                          "r"(av_cur[i].z), "r"(av_cur[i].w),
                          "r"(bv.x), "r"(bv.y));
                }
            }
            #pragma unroll
            for (int i = 0; i < 4; i++) av_cur[i] = av_nxt[i];
        }
    }

    // ---- store: c0,c1 -> (row g, px 2tg..2tg+1), c2,c3 -> (row g+8, ...)
    float* ob = out + ((size_t)b * CH * HH + h) * WW;
    #pragma unroll
    for (int i = 0; i < 4; i++) {
        int co = wm * 64 + i * 16 + g;
        #pragma unroll
        for (int j = 0; j < 7; j++) {
            int w = wn * 56 + j * 8 + tg * 2;
            *(float2*)&ob[(size_t)co * HW + w] =
                make_float2(acc[i][j][0], acc[i][j][1]);
            *(float2*)&ob[(size_t)(co + 8) * HW + w] =
                make_float2(acc[i][j][2], acc[i][j][3]);
        }
    }
}

// ---------------------------------------------------------------------------
extern "C" void kernel_launch(void* const* d_in, const int* in_sizes, int n_in,
                              void* d_out, int out_size) {
    const float* x = (const float*)d_in[0];   // (16,128,112,112)
    const float* W = (const float*)d_in[1];   // (128,128,3,3)
    const float* b = (const float*)d_in[2];   // (128,)
    float* out = (float*)d_out;

    // Launch order puts conv_kernel at index 3 so ncu captures it.
    gb_kernel<<<1, 256>>>(b);
    xt_kernel<<<dim3(HH / 2, 8, BATCH), 256>>>(x);
    w2_kernel<<<1152, 128>>>(W);
    conv_kernel<<<dim3(HH, BATCH), 128>>>(out);
}

// round 15
// speedup vs baseline: 1.3913x; 1.3913x over previous
#include <cuda_runtime.h>
#include <cuda_fp16.h>
#include <cstdint>

#define BATCH 16
#define CH 128          // channels == time steps == out channels
#define HH 112
#define WW 112
#define HW (HH * WW)

// ---------------- device globals (no allocation allowed) ----------------
__device__ float  g_G[256];
__device__ float  g_Bp[CH];
// A fragments (fused weights) in m16n8k16 A layout, fp16:
// [tap 9][cb 8][mtile 8][lane 32][8 halfs = a0..a3]
__device__ __half g_AFh[9 * 8 * 8 * 32 * 8];          // 294912 B
// Transposed fp16 x: [cb 8][b 16][h 112][w 112][ci16 permuted] as half2 pairs
__device__ __half2 g_Xt[(size_t)8 * BATCH * HH * WW * 8];   // 51.4 MB

__device__ __forceinline__ uint32_t smem_u32(const void* p) {
    uint32_t a;
    asm("{ .reg .u64 t; cvta.to.shared.u64 t, %1; cvt.u32.u64 %0, t; }" : "=r"(a) : "l"(p));
    return a;
}

// ---------------------------------------------------------------------------
// Merged: G[m] = (l conv k)[m] (alpha == beta == exp(-1) exactly), then
// fused bias Bp[t] = sum_o G[(t-o)&255] * b[o]. Single block.
// ---------------------------------------------------------------------------
__global__ void gb_kernel(const float* __restrict__ b) {
    __shared__ float Gs[256];
    int m = threadIdx.x;  // 256
    const float beta = 0.36787944117144233f;
    int lo = max(0, m - 127), hi = min(m, 127);
    int cnt = hi - lo + 1;
    float gv = (cnt > 0) ? (1.0f - beta) * expf(-(float)m) * (float)cnt : 0.0f;
    g_G[m] = gv;
    Gs[m] = gv;
    __syncthreads();
    if (m < CH) {
        float s = 0.0f;
        #pragma unroll 8
        for (int o = 0; o < CH; o++) s += Gs[(m - o) & 255] * b[o];
        g_Bp[m] = s;
    }
}

// ---------------------------------------------------------------------------
// Fused weights scattered into mma.m16n8k16 A-fragment layout (fp16).
// Wp[co][ci][tap] = sum_o G[(co-o)&255] * W[o][ci][tap]
// ---------------------------------------------------------------------------
__global__ void w2_kernel(const float* __restrict__ W) {
    __shared__ float Ws[128];
    __shared__ float Gs[256];
    int blk = blockIdx.x;               // ci*9 + tap : 1152 blocks
    int ci = blk / 9, tap = blk - ci * 9;
    int co = threadIdx.x;               // 128 threads
    Ws[co] = W[co * 1152 + ci * 9 + tap];
    Gs[co] = g_G[co];
    Gs[co + 128] = g_G[co + 128];
    __syncthreads();
    float s = 0.0f;
    #pragma unroll 8
    for (int o = 0; o < 128; o++) s += Gs[(co - o) & 255] * Ws[o];

    int r = co & 15, mt = co >> 4;
    int g = r & 7, rh = r >> 3;                 // rh -> a1/a3 (row+8)
    int kc = ci >> 4, c16 = ci & 15;
    int tg = (c16 >> 1) & 3, bslot = c16 & 1, c = c16 >> 3;   // c -> k+8 (a2/a3)
    int reg = rh + 2 * c;
    int lane = g * 4 + tg;
    g_AFh[((((size_t)tap * 8 + kc) * 8 + mt) * 32 + lane) * 8 + reg * 2 + bslot] =
        __float2half_rn(s);
}

// ---------------------------------------------------------------------------
// Transpose x -> fp16 [cb][b][h][w][ci16 perm] (32B per w).
// 2 h-rows per 256-thread block: 896B contiguous reads, 2x7168B writes.
// half2 slot p2 = tg*2 + c holds (ci, ci+1), ci = 2*tg + 8*c.
// ---------------------------------------------------------------------------
__global__ void xt_kernel(const float* __restrict__ x) {
    __shared__ float t[16][2][116];
    int h0 = blockIdx.x * 2, cb = blockIdx.y, b = blockIdx.z;
    int tid = threadIdx.x;   // 256
    const float* xp = x + ((size_t)b * CH + cb * 16) * HW + h0 * WW;
    // 16 ci x 56 float4 (rows h0, h0+1 are contiguous: 224 floats per ci)
    for (int i = tid; i < 16 * 56; i += 256) {
        int ci = i / 56, k = i - ci * 56;
        int hh = (k >= 28) ? 1 : 0;
        int w4 = k - hh * 28;
        ((float4*)t[ci][hh])[w4] =
            *(const float4*)(xp + (size_t)ci * HW + hh * WW + w4 * 4);
    }
    __syncthreads();
    // 448 slots: (hh, w, half16B). 8 LDS + 4 cvt + 1 STG.128 per slot.
    for (int i = tid; i < 448; i += 256) {
        int hh = (i >= 224) ? 1 : 0;
        int j = i - hh * 224;
        int w = j >> 1, hf = j & 1;
        uint32_t h2[4];
        #pragma unroll
        for (int q = 0; q < 4; q++) {
            int p2 = hf * 4 + q;
            int tg = p2 >> 1, c = p2 & 1;
            int ca = 2 * tg + 8 * c;
            __half2 v = __floats2half2_rn(t[ca][hh][w], t[ca + 1][hh][w]);
            h2[q] = *(uint32_t*)&v;
        }
        __half2* dst = g_Xt + ((((size_t)cb * BATCH + b) * HH + h0 + hh) * WW) * 8;
        *((uint4*)(dst + (size_t)w * 8) + hf) = make_uint4(h2[0], h2[1], h2[2], h2[3]);
    }
}

// ---------------------------------------------------------------------------
// Main conv: implicit GEMM on mma.sync.m16n8k16 fp16 (f32 accum).
// CTA = (b, h), 128 threads, 4 warps in 2M x 2N; warp tile 64co x 56px.
// R10 loop structure: stage(cb+1) BEFORE wait_group 1 (overlap), 2 syncs.
// A fragments register-double-buffered across taps.
// ---------------------------------------------------------------------------
#define XBUF_BYTES 11520        // 3 * 120 * 32
#define NSLOT 720               // 3 * 120 * 2 (16B slots)

__global__ __launch_bounds__(128, 2) void conv_kernel(float* __restrict__ out) {
    __shared__ __align__(16) char xsm[2][XBUF_BYTES];
    __shared__ int otab[NSLOT];

    const int tid = threadIdx.x, wid = tid >> 5, lane = tid & 31;
    const int g = lane >> 2, tg = lane & 3;
    const int wm = wid >> 1, wn = wid & 1;    // 2x2 warp grid
    const int b = blockIdx.y;
    const int h = blockIdx.x;

    // ---- offset table (each thread writes and later reads the SAME indices)
    for (int i = tid; i < NSLOT; i += 128) {
        int blk = i & 1;
        int w = (i >> 1) % 120;
        int row = (i >> 1) / 120;
        int gh = h - 1 + row;
        int gw = w - 1;
        bool ok = ((unsigned)gh < (unsigned)HH) & ((unsigned)gw < (unsigned)WW);
        otab[i] = ok ? ((gh * WW + gw) * 32 + blk * 16) : -1;
    }

    // accumulators initialized with fused bias
    float acc[4][7][4];
    #pragma unroll
    for (int i = 0; i < 4; i++) {
        float blo = g_Bp[wm * 64 + i * 16 + g];
        float bhi = g_Bp[wm * 64 + i * 16 + g + 8];
        #pragma unroll
        for (int j = 0; j < 7; j++) {
            acc[i][j][0] = blo; acc[i][j][1] = blo;
            acc[i][j][2] = bhi; acc[i][j][3] = bhi;
        }
    }

    const uint4* AF4 = (const uint4*)g_AFh;
    const uint32_t xs_b = smem_u32(&xsm[0][0]);
    const char* xtb = (const char*)g_Xt;

    // ---- async stage one 16-ci chunk (fp16, 16B contiguous copies)
    auto stage = [&](int cb, int buf) {
        const char* src_base = xtb + (((size_t)cb * BATCH + b) * HH) * WW * 32;
        uint32_t d = xs_b + (uint32_t)buf * XBUF_BYTES + (uint32_t)tid * 16;
        #pragma unroll
        for (int it = 0; it < 6; it++) {
            int i = tid + it * 128;
            if (i < NSLOT) {
                int off = otab[i];
                const char* src = src_base + (off >= 0 ? off : 0);
                int sz = (off >= 0) ? 16 : 0;
                asm volatile("cp.async.ca.shared.global [%0], [%1], 16, %2;"
                             :: "r"(d), "l"(src), "r"(sz));
            }
            d += 2048;
        }
        asm volatile("cp.async.commit_group;" ::: "memory");
    };

    // A-fragment load for (tap, cb): 4 consecutive mtiles for this warp
    auto aload = [&](int tap, int cb, uint4* av) {
        #pragma unroll
        for (int i = 0; i < 4; i++)
            av[i] = __ldg(&AF4[(((size_t)tap * 8 + cb) * 8 + wm * 4 + i) * 32 + lane]);
    };

    stage(0, 0);   // prologue

    uint4 av_cur[4], av_nxt[4];
    aload(0, 0, av_cur);   // prefetch first tap

    for (int cb = 0; cb < 8; cb++) {
        if (cb + 1 < 8) stage(cb + 1, (cb + 1) & 1);
        if (cb < 7) asm volatile("cp.async.wait_group 1;" ::: "memory");
        else        asm volatile("cp.async.wait_group 0;" ::: "memory");
        __syncthreads();

        // per-warp/lane B base: [row][w = wn*56 + g + (j*8+kw)][p = tg*4]
        const char* bp = &xsm[cb & 1][0] + (wn * 56 + g) * 32 + tg * 8;

        #pragma unroll
        for (int tap = 0; tap < 9; tap++) {
            // prefetch next tap's A fragments (cross chunk boundary)
            int ntap = (tap == 8) ? 0 : tap + 1;
            int ncb  = (tap == 8) ? ((cb + 1) & 7) : cb;
            aload(ntap, ncb, av_nxt);

            const int kh = tap / 3, kw = tap - kh * 3;
            #pragma unroll
            for (int j = 0; j < 7; j++) {
                // one LDS.64: {b0 = ci 2tg..2tg+1, b1 = ci 2tg+8..2tg+9}
                uint2 bv = *(const uint2*)(bp + kh * 3840 + (j * 8 + kw) * 32);
                #pragma unroll
                for (int i = 0; i < 4; i++) {
                    asm volatile(
                        "mma.sync.aligned.m16n8k16.row.col.f32.f16.f16.f32 "
                        "{%0,%1,%2,%3}, {%4,%5,%6,%7}, {%8,%9}, {%0,%1,%2,%3};"
                        : "+f"(acc[i][j][0]), "+f"(acc[i][j][1]),
                          "+f"(acc[i][j][2]), "+f"(acc[i][j][3])
                        : "r"(av_cur[i].x), "r"(av_cur[i].y),
                          "r"(av_cur[i].z), "r"(av_cur[i].w),
                          "r"(bv.x), "r"(bv.y));
                }
            }
            #pragma unroll
            for (int i = 0; i < 4; i++) av_cur[i] = av_nxt[i];
        }
        __syncthreads();
    }

    // ---- store: c0,c1 -> (row g, px 2tg..2tg+1), c2,c3 -> (row g+8, ...)
    float* ob = out + ((size_t)b * CH * HH + h) * WW;
    #pragma unroll
    for (int i = 0; i < 4; i++) {
        int co = wm * 64 + i * 16 + g;
        #pragma unroll
        for (int j = 0; j < 7; j++) {
            int w = wn * 56 + j * 8 + tg * 2;
            *(float2*)&ob[(size_t)co * HW + w] =
                make_float2(acc[i][j][0], acc[i][j][1]);
            *(float2*)&ob[(size_t)(co + 8) * HW + w] =
                make_float2(acc[i][j][2], acc[i][j][3]);
        }
    }
}

// ---------------------------------------------------------------------------
extern "C" void kernel_launch(void* const* d_in, const int* in_sizes, int n_in,
                              void* d_out, int out_size) {
    const float* x = (const float*)d_in[0];   // (16,128,112,112)
    const float* W = (const float*)d_in[1];   // (128,128,3,3)
    const float* b = (const float*)d_in[2];   // (128,)
    float* out = (float*)d_out;

    // Launch order puts conv_kernel at index 3 so ncu captures it.
    gb_kernel<<<1, 256>>>(b);
    xt_kernel<<<dim3(HH / 2, 8, BATCH), 256>>>(x);
    w2_kernel<<<1152, 128>>>(W);
    conv_kernel<<<dim3(HH, BATCH), 128>>>(out);
}

// round 16
// speedup vs baseline: 1.4307x; 1.0284x over previous
#include <cuda_runtime.h>
#include <cuda_fp16.h>
#include <cstdint>

#define BATCH 16
#define CH 128          // channels == time steps == out channels
#define HH 112
#define WW 112
#define HW (HH * WW)

// ---------------- device globals (no allocation allowed) ----------------
__device__ float  g_G[256];
__device__ float  g_Bp[CH];
// A fragments (fused weights) in m16n8k16 A layout, fp16:
// [tap 9][cb 8][mtile 8][lane 32][8 halfs = a0..a3]
__device__ __half g_AFh[9 * 8 * 8 * 32 * 8];          // 294912 B
// Transposed fp16 x: [cb 8][b 16][h 112][w 112][ci16 permuted] as half2 pairs
__device__ __half2 g_Xt[(size_t)8 * BATCH * HH * WW * 8];   // 51.4 MB

__device__ __forceinline__ uint32_t smem_u32(const void* p) {
    uint32_t a;
    asm("{ .reg .u64 t; cvta.to.shared.u64 t, %1; cvt.u32.u64 %0, t; }" : "=r"(a) : "l"(p));
    return a;
}

// ---------------------------------------------------------------------------
// Merged: G[m] = (l conv k)[m] (alpha == beta == exp(-1) exactly), then
// fused bias Bp[t] = sum_o G[(t-o)&255] * b[o]. Single block.
// ---------------------------------------------------------------------------
__global__ void gb_kernel(const float* __restrict__ b) {
    __shared__ float Gs[256];
    int m = threadIdx.x;  // 256
    const float beta = 0.36787944117144233f;
    int lo = max(0, m - 127), hi = min(m, 127);
    int cnt = hi - lo + 1;
    float gv = (cnt > 0) ? (1.0f - beta) * expf(-(float)m) * (float)cnt : 0.0f;
    g_G[m] = gv;
    Gs[m] = gv;
    __syncthreads();
    if (m < CH) {
        float s = 0.0f;
        #pragma unroll 8
        for (int o = 0; o < CH; o++) s += Gs[(m - o) & 255] * b[o];
        g_Bp[m] = s;
    }
}

// ---------------------------------------------------------------------------
// Fused weights scattered into mma.m16n8k16 A-fragment layout (fp16).
// Wp[co][ci][tap] = sum_o G[(co-o)&255] * W[o][ci][tap]
// ---------------------------------------------------------------------------
__global__ void w2_kernel(const float* __restrict__ W) {
    __shared__ float Ws[128];
    __shared__ float Gs[256];
    int blk = blockIdx.x;               // ci*9 + tap : 1152 blocks
    int ci = blk / 9, tap = blk - ci * 9;
    int co = threadIdx.x;               // 128 threads
    Ws[co] = W[co * 1152 + ci * 9 + tap];
    Gs[co] = g_G[co];
    Gs[co + 128] = g_G[co + 128];
    __syncthreads();
    float s = 0.0f;
    #pragma unroll 8
    for (int o = 0; o < 128; o++) s += Gs[(co - o) & 255] * Ws[o];

    int r = co & 15, mt = co >> 4;
    int g = r & 7, rh = r >> 3;                 // rh -> a1/a3 (row+8)
    int kc = ci >> 4, c16 = ci & 15;
    int tg = (c16 >> 1) & 3, bslot = c16 & 1, c = c16 >> 3;   // c -> k+8 (a2/a3)
    int reg = rh + 2 * c;
    int lane = g * 4 + tg;
    g_AFh[((((size_t)tap * 8 + kc) * 8 + mt) * 32 + lane) * 8 + reg * 2 + bslot] =
        __float2half_rn(s);
}

// ---------------------------------------------------------------------------
// Transpose x -> fp16 [cb][b][h][w][ci16 perm] (32B per w).
// 2 h-rows per 256-thread block.
// ---------------------------------------------------------------------------
__global__ void xt_kernel(const float* __restrict__ x) {
    __shared__ float t[16][2][116];
    int h0 = blockIdx.x * 2, cb = blockIdx.y, b = blockIdx.z;
    int tid = threadIdx.x;   // 256
    const float* xp = x + ((size_t)b * CH + cb * 16) * HW + h0 * WW;
    for (int i = tid; i < 16 * 56; i += 256) {
        int ci = i / 56, k = i - ci * 56;
        int hh = (k >= 28) ? 1 : 0;
        int w4 = k - hh * 28;
        ((float4*)t[ci][hh])[w4] =
            *(const float4*)(xp + (size_t)ci * HW + hh * WW + w4 * 4);
    }
    __syncthreads();
    for (int i = tid; i < 448; i += 256) {
        int hh = (i >= 224) ? 1 : 0;
        int j = i - hh * 224;
        int w = j >> 1, hf = j & 1;
        uint32_t h2[4];
        #pragma unroll
        for (int q = 0; q < 4; q++) {
            int p2 = hf * 4 + q;
            int tg = p2 >> 1, c = p2 & 1;
            int ca = 2 * tg + 8 * c;
            __half2 v = __floats2half2_rn(t[ca][hh][w], t[ca + 1][hh][w]);
            h2[q] = *(uint32_t*)&v;
        }
        __half2* dst = g_Xt + ((((size_t)cb * BATCH + b) * HH + h0 + hh) * WW) * 8;
        *((uint4*)(dst + (size_t)w * 8) + hf) = make_uint4(h2[0], h2[1], h2[2], h2[3]);
    }
}

// ---------------------------------------------------------------------------
// Main conv: implicit GEMM on mma.sync.m16n8k16 fp16 (f32 accum).
// CTA = (b, h), 128 threads, 4 warps 2M x 2N; warp tile 64co x 56px.
// K-chunking: 4 chunks x 32 ci (two 16-ci groups per buffer) -> half the
// barrier/wait boundaries, 2x compute window per staged copy.
// ---------------------------------------------------------------------------
#define KSB 11520               // bytes per 16-ci group (3*120*32)
#define XBUF_BYTES (2 * KSB)    // 23040: one 32-ci chunk
#define NSLOT 720               // 16B slots per 16-ci group

__global__ __launch_bounds__(128, 2) void conv_kernel(float* __restrict__ out) {
    __shared__ __align__(16) char xsm[2][XBUF_BYTES];   // 46080 B
    __shared__ int otab[NSLOT];                         // + 2880 B = 48960

    const int tid = threadIdx.x, wid = tid >> 5, lane = tid & 31;
    const int g = lane >> 2, tg = lane & 3;
    const int wm = wid >> 1, wn = wid & 1;    // 2x2 warp grid
    const int b = blockIdx.y;
    const int h = blockIdx.x;

    // ---- offset table (same for both 16-ci groups; plane base differs)
    for (int i = tid; i < NSLOT; i += 128) {
        int blk = i & 1;
        int w = (i >> 1) % 120;
        int row = (i >> 1) / 120;
        int gh = h - 1 + row;
        int gw = w - 1;
        bool ok = ((unsigned)gh < (unsigned)HH) & ((unsigned)gw < (unsigned)WW);
        otab[i] = ok ? ((gh * WW + gw) * 32 + blk * 16) : -1;
    }

    // accumulators initialized with fused bias
    float acc[4][7][4];
    #pragma unroll
    for (int i = 0; i < 4; i++) {
        float blo = g_Bp[wm * 64 + i * 16 + g];
        float bhi = g_Bp[wm * 64 + i * 16 + g + 8];
        #pragma unroll
        for (int j = 0; j < 7; j++) {
            acc[i][j][0] = blo; acc[i][j][1] = blo;
            acc[i][j][2] = bhi; acc[i][j][3] = bhi;
        }
    }

    const uint4* AF4 = (const uint4*)g_AFh;
    const uint32_t xs_b = smem_u32(&xsm[0][0]);
    const char* xtb = (const char*)g_Xt;

    // ---- async stage one 32-ci chunk (two 16-ci groups)
    auto stage = [&](int ch, int buf) {
        #pragma unroll
        for (int ks = 0; ks < 2; ks++) {
            const char* src_base =
                xtb + (((size_t)(ch * 2 + ks) * BATCH + b) * HH) * WW * 32;
            uint32_t d = xs_b + (uint32_t)buf * XBUF_BYTES + (uint32_t)ks * KSB
                       + (uint32_t)tid * 16;
            #pragma unroll
            for (int it = 0; it < 6; it++) {
                int i = tid + it * 128;
                if (i < NSLOT) {
                    int off = otab[i];
                    const char* src = src_base + (off >= 0 ? off : 0);
                    int sz = (off >= 0) ? 16 : 0;
                    asm volatile("cp.async.ca.shared.global [%0], [%1], 16, %2;"
                                 :: "r"(d), "l"(src), "r"(sz));
                }
                d += 2048;
            }
        }
        asm volatile("cp.async.commit_group;" ::: "memory");
    };

    // A-fragment load for (tap, cb): 4 consecutive mtiles for this warp
    auto aload = [&](int tap, int cb, uint4* av) {
        #pragma unroll
        for (int i = 0; i < 4; i++)
            av[i] = __ldg(&AF4[(((size_t)tap * 8 + cb) * 8 + wm * 4 + i) * 32 + lane]);
    };

    stage(0, 0);   // prologue

    uint4 av_cur[4], av_nxt[4];
    aload(0, 0, av_cur);   // prefetch first (ks=0, tap=0) of chunk 0

    for (int ch = 0; ch < 4; ch++) {
        if (ch + 1 < 4) stage(ch + 1, (ch + 1) & 1);
        if (ch < 3) asm volatile("cp.async.wait_group 1;" ::: "memory");
        else        asm volatile("cp.async.wait_group 0;" ::: "memory");
        __syncthreads();

        #pragma unroll
        for (int ks = 0; ks < 2; ks++) {
            const int cb = ch * 2 + ks;
            // per-warp/lane B base for this 16-ci group
            const char* bp = &xsm[ch & 1][0] + ks * KSB
                           + (wn * 56 + g) * 32 + tg * 8;

            #pragma unroll
            for (int tap = 0; tap < 9; tap++) {
                // prefetch next (ks,tap) A fragments (cross boundaries)
                int ntap, ncb;
                if (tap < 8)      { ntap = tap + 1; ncb = cb; }
                else if (ks == 0) { ntap = 0;       ncb = cb + 1; }
                else              { ntap = 0;       ncb = (ch == 3) ? 0 : (ch + 1) * 2; }
                aload(ntap, ncb, av_nxt);

                const int kh = tap / 3, kw = tap - kh * 3;
                #pragma unroll
                for (int j = 0; j < 7; j++) {
                    // one LDS.64: {b0 = ci 2tg..2tg+1, b1 = ci 2tg+8..2tg+9}
                    uint2 bv = *(const uint2*)(bp + kh * 3840 + (j * 8 + kw) * 32);
                    #pragma unroll
                    for (int i = 0; i < 4; i++) {
                        asm volatile(
                            "mma.sync.aligned.m16n8k16.row.col.f32.f16.f16.f32 "
                            "{%0,%1,%2,%3}, {%4,%5,%6,%7}, {%8,%9}, {%0,%1,%2,%3};"
                            : "+f"(acc[i][j][0]), "+f"(acc[i][j][1]),
                              "+f"(acc[i][j][2]), "+f"(acc[i][j][3])
                            : "r"(av_cur[i].x), "r"(av_cur[i].y),
                              "r"(av_cur[i].z), "r"(av_cur[i].w),
                              "r"(bv.x), "r"(bv.y));
                    }
                }
                #pragma unroll
                for (int i = 0; i < 4; i++) av_cur[i] = av_nxt[i];
            }
        }
        __syncthreads();
    }

    // ---- store: c0,c1 -> (row g, px 2tg..2tg+1), c2,c3 -> (row g+8, ...)
    float* ob = out + ((size_t)b * CH * HH + h) * WW;
    #pragma unroll
    for (int i = 0; i < 4; i++) {
        int co = wm * 64 + i * 16 + g;
        #pragma unroll
        for (int j = 0; j < 7; j++) {
            int w = wn * 56 + j * 8 + tg * 2;
            *(float2*)&ob[(size_t)co * HW + w] =
                make_float2(acc[i][j][0], acc[i][j][1]);
            *(float2*)&ob[(size_t)(co + 8) * HW + w] =
                make_float2(acc[i][j][2], acc[i][j][3]);
        }
    }
}

// ---------------------------------------------------------------------------
extern "C" void kernel_launch(void* const* d_in, const int* in_sizes, int n_in,
                              void* d_out, int out_size) {
    const float* x = (const float*)d_in[0];   // (16,128,112,112)
    const float* W = (const float*)d_in[1];   // (128,128,3,3)
    const float* b = (const float*)d_in[2];   // (128,)
    float* out = (float*)d_out;

    // Launch order puts conv_kernel at index 3 so ncu captures it.
    gb_kernel<<<1, 256>>>(b);
    xt_kernel<<<dim3(HH / 2, 8, BATCH), 256>>>(x);
    w2_kernel<<<1152, 128>>>(W);
    conv_kernel<<<dim3(HH, BATCH), 128>>>(out);
}